// round 16
// baseline (speedup 1.0000x reference)
#include <cuda_runtime.h>
#include <cuda_bf16.h>
#include <math_constants.h>

// Problem constants (fixed by setup_inputs)
#define Bq 4
#define Hq 8
#define BH 32          // B*H
#define Lq 2048
#define Dq 64
#define SK 40          // sample_k
#define NT 40          // n_top
#define NS 32          // key splits in flash kernel (64 keys each)
#define SCALE 0.125f   // 1/sqrt(64)

// ---------------- scratch (device globals; no allocation) ----------------
__device__ float g_M[BH * Lq];                 // 256 KB
__device__ int   g_top[BH * NT];               // 5 KB
__device__ float g_vmean[BH * Dq];             // 8 KB
__device__ float g_pm[NS * BH * NT];           // per-split row max
__device__ float g_psum[NS * BH * NT];         // per-split exp-sum
__device__ float g_part[(size_t)NS * BH * NT * Dq];  // 10.5 MB partial ctx

// Fast exp on the FMA pipe: exp(x) = 2^(x*log2e), deg-6 poly + exponent bits.
__device__ __forceinline__ float fexpf(float x) {
    float y = x * 1.4426950408889634f;
    y = fmaxf(y, -125.0f);
    float r = rintf(y);
    float f = y - r;
    float p = 1.5403530e-4f;
    p = fmaf(p, f, 1.3333558e-3f);
    p = fmaf(p, f, 9.6181291e-3f);
    p = fmaf(p, f, 5.5504109e-2f);
    p = fmaf(p, f, 2.4022651e-1f);
    p = fmaf(p, f, 6.9314718e-1f);
    p = fmaf(p, f, 1.0f);
    return p * __int_as_float(((int)r + 127) << 23);
}

// ---------------- fold: transpose-reduce (V arrays, V/2 shuffles) --------
template<int O, int V>
__device__ __forceinline__ void fold(float* p, int lane) {
    bool hi = (lane & O) != 0;
    #pragma unroll
    for (int j = 0; j < V / 2; j++) {
        float send = hi ? p[j] : p[j + V / 2];
        float keep = hi ? p[j + V / 2] : p[j];
        p[j] = keep + __shfl_xor_sync(0xffffffffu, send, O);
    }
}

// ---------------- kernel 1: M[bh,l] = max_s q.k - sum_s/L ----------------
// Warp per query. Paired-row gathers: lanes 0-15 load sample 2j's key row
// (float4/lane), lanes 16-31 load sample 2j+1's row -> 20 LDG.128 + 24
// broadcasts + 20 fold shuffles (vs 40 LDG.64 + 40 + 66 before).
__global__ void k_M(const float* __restrict__ Q, const float* __restrict__ K,
                    const int* __restrict__ idxs) {
    int w = blockIdx.x * 8 + (threadIdx.x >> 5);   // query id (bh*2048 + l)
    int lane = threadIdx.x & 31;
    int bh = w >> 11;
    int l  = w & (Lq - 1);
    int hl = lane >> 4;            // row-in-pair selector
    int dl = lane & 15;            // dim quad within the row
    float4 q = ((const float4*)(Q + (size_t)w * Dq))[dl];
    const float* Kb = K + (size_t)bh * Lq * Dq;
    int e0 = idxs[l * SK + lane];                       // samples 0..31
    int e1 = (lane < 8) ? idxs[l * SK + 32 + lane] : 0; // samples 32..39

    float p[16];
    #pragma unroll
    for (int j = 0; j < 16; j++) {   // pair j: samples 2j (lo half), 2j+1 (hi)
        int idx = __shfl_sync(0xffffffffu, e0, 2 * j + hl);
        float4 k = ((const float4*)(Kb + (size_t)idx * Dq))[dl];
        p[j] = fmaf(q.x, k.x, fmaf(q.y, k.y, fmaf(q.z, k.z, q.w * k.w)));
    }
    float p2[4];
    #pragma unroll
    for (int m = 0; m < 4; m++) {    // pair m: samples 32+2m, 33+2m
        int idx = __shfl_sync(0xffffffffu, e1, 2 * m + hl);
        float4 k = ((const float4*)(Kb + (size_t)idx * Dq))[dl];
        p2[m] = fmaf(q.x, k.x, fmaf(q.y, k.y, fmaf(q.z, k.z, q.w * k.w)));
    }
    // chain 1: 16 arrays -> 1; sums lane bits 3,2,1,0 (dims); 32 samples,
    // one per lane (bits 4..0 encode sample id).
    fold<8, 16>(p, lane);
    fold<4, 8>(p, lane);
    fold<2, 4>(p, lane);
    fold<1, 2>(p, lane);
    // chain 2: 4 arrays -> 1 (bits 3,2 summed), then bits 1,0 (replicated x4)
    fold<8, 4>(p2, lane);
    fold<4, 2>(p2, lane);
    p2[0] += __shfl_xor_sync(0xffffffffu, p2[0], 2);
    p2[0] += __shfl_xor_sync(0xffffffffu, p2[0], 1);

    float mx = fmaxf(p[0], p2[0]);
    float sm = p[0] + 0.25f * p2[0];   // p2 replicated x4 -> exact weight
    #pragma unroll
    for (int o = 16; o; o >>= 1) {
        mx = fmaxf(mx, __shfl_xor_sync(0xffffffffu, mx, o));
        sm += __shfl_xor_sync(0xffffffffu, sm, o);
    }
    if (lane == 0) g_M[w] = mx - sm * (1.0f / (float)Lq);
}

// ---------------- kernel 2: top-40 per (b,h), 4-level radix select -------
__global__ void k_topk() {
    __shared__ int hist[8][256];
    __shared__ int suf[257];
    __shared__ int wred[8];
    __shared__ int s_T, s_cnt, s_min;
    int bh = blockIdx.x;
    int t = threadIdx.x, lane = t & 31, w = t >> 5;

    unsigned key[8];
    #pragma unroll
    for (int j = 0; j < 8; j++) {
        unsigned u = __float_as_uint(g_M[bh * Lq + t * 8 + j]);
        key[j] = (u & 0x80000000u) ? ~u : (u | 0x80000000u);
    }
    unsigned prefix = 0;
    int need = NT;
    if (t == 0) s_cnt = 0;

    #pragma unroll
    for (int level = 0; level < 4; level++) {
        int shift = 24 - 8 * level;
        for (int b = t; b < 8 * 256; b += 256) (&hist[0][0])[b] = 0;
        __syncthreads();
        #pragma unroll
        for (int j = 0; j < 8; j++) {
            bool match = (level == 0) || ((key[j] >> (shift + 8)) == prefix);
            if (match) atomicAdd(&hist[w][(key[j] >> shift) & 255u], 1);
        }
        __syncthreads();
        int h = 0;
        #pragma unroll
        for (int ww = 0; ww < 8; ww++) h += hist[ww][t];
        int sv = h;
        #pragma unroll
        for (int off = 1; off < 32; off <<= 1) {
            int v = __shfl_down_sync(0xffffffffu, sv, off);
            if (lane + off < 32) sv += v;
        }
        int wtot = __shfl_sync(0xffffffffu, sv, 0);
        if (lane == 0) wred[w] = wtot;
        __syncthreads();
        int higher = 0;
        #pragma unroll
        for (int ww = 0; ww < 8; ww++) if (ww > w) higher += wred[ww];
        suf[t] = sv + higher;
        if (t == 0) suf[256] = 0;
        __syncthreads();
        if (suf[t] >= need && suf[t + 1] < need) s_T = t;
        __syncthreads();
        int T = s_T;
        #pragma unroll
        for (int j = 0; j < 8; j++) {
            bool match = (level == 0) || ((key[j] >> (shift + 8)) == prefix);
            if (match && (int)((key[j] >> shift) & 255u) > T) {
                int p = atomicAdd(&s_cnt, 1);
                g_top[bh * NT + p] = t * 8 + j;
            }
        }
        need -= suf[T + 1];
        prefix = (prefix << 8) | (unsigned)T;
        __syncthreads();
    }

    for (int it = 0; it < need; it++) {
        int mi = Lq;
        #pragma unroll
        for (int j = 0; j < 8; j++)
            if (key[j] == prefix) mi = min(mi, t * 8 + j);
        #pragma unroll
        for (int off = 16; off; off >>= 1)
            mi = min(mi, __shfl_xor_sync(0xffffffffu, mi, off));
        if (lane == 0) wred[w] = mi;
        __syncthreads();
        if (t == 0) {
            int m = wred[0];
            #pragma unroll
            for (int ww = 1; ww < 8; ww++) m = min(m, wred[ww]);
            s_min = m;
            g_top[bh * NT + (NT - need) + it] = m;
        }
        __syncthreads();
        int m = s_min;
        if (m >= t * 8 && m < t * 8 + 8) key[m - t * 8] = 0u;
        __syncthreads();
    }
}

// ---------------- kernel 3: V mean over L per (b,h), float4 --------------
__global__ void k_vmean(const float* __restrict__ V) {
    __shared__ float4 ps[256];
    int bh = blockIdx.x;
    int t = threadIdx.x;
    int d4 = t & 15, part = t >> 4;
    const float4* Vb = (const float4*)(V + (size_t)bh * Lq * Dq);
    float4 s = make_float4(0.f, 0.f, 0.f, 0.f);
    int k0 = part * 128;
    for (int k = k0; k < k0 + 128; k++) {
        float4 v = Vb[(size_t)k * 16 + d4];
        s.x += v.x; s.y += v.y; s.z += v.z; s.w += v.w;
    }
    ps[t] = s;
    __syncthreads();
    if (t < 16) {
        float4 a = ps[t];
        #pragma unroll
        for (int pI = 1; pI < 16; pI++) {
            float4 v = ps[pI * 16 + t];
            a.x += v.x; a.y += v.y; a.z += v.z; a.w += v.w;
        }
        const float inv = 1.0f / (float)Lq;
        a.x *= inv; a.y *= inv; a.z *= inv; a.w *= inv;
        ((float4*)g_vmean)[bh * 16 + t] = a;
    }
}

// ---------------- kernel 4: broadcast V_mean (2 half launches) -----------
__global__ void k_fill(float4* __restrict__ out4, int base) {
    int i = base + blockIdx.x * 256 + threadIdx.x;
    int bh = i >> 15;
    int d4 = i & 15;
    out4[i] = ((const float4*)g_vmean)[bh * 16 + d4];
}

// ---------------- kernel 5: fused flash attention over 64-key split ------
// grid = BH * NS = 1024 blocks, 256 threads (round-12 measured config).
__global__ void k_flash(const float* __restrict__ Q,
                        const float* __restrict__ K,
                        const float* __restrict__ V) {
    __shared__ float qs[NT * Dq];      // 10 KB
    __shared__ float Kt[Dq * 68];      // 17 KB, transposed [d][k]; reused as P
    __shared__ float Vs[64 * Dq];      // 16 KB
    int bh = blockIdx.x >> 5;
    int ks = blockIdx.x & 31;
    int t = threadIdx.x;               // 256
    const float* Qb = Q + (size_t)bh * Lq * Dq;
    const float* Kb = K + (size_t)bh * Lq * Dq;
    const float* Vb = V + (size_t)bh * Lq * Dq;
    for (int j = t; j < NT * Dq; j += 256) {
        int u = j >> 6, d = j & 63;
        int qi = __ldg(&g_top[bh * NT + u]);
        qs[j] = Qb[(size_t)qi * Dq + d];
    }
    for (int j = t; j < 64 * Dq; j += 256) {
        int r = j >> 6, d = j & 63;
        Kt[d * 68 + r] = Kb[(size_t)(ks * 64 + r) * Dq + d];
    }
    for (int j = t; j < 64 * Dq; j += 256) Vs[j] = Vb[(size_t)ks * 64 * Dq + j];
    __syncthreads();

    int w = t >> 5, lane = t & 31;     // warp w: queries w*5..w*5+4; lane: 2 keys
    float acc[5][2] = {};
    #pragma unroll
    for (int dc = 0; dc < Dq; dc += 4) {
        float4 a[5];
        #pragma unroll
        for (int i = 0; i < 5; i++)
            a[i] = *(const float4*)&qs[(w * 5 + i) * Dq + dc];
        #pragma unroll
        for (int j = 0; j < 4; j++) {
            float2 b = *(const float2*)&Kt[(dc + j) * 68 + lane * 2];
            #pragma unroll
            for (int i = 0; i < 5; i++) {
                float aj = (j == 0) ? a[i].x : (j == 1) ? a[i].y : (j == 2) ? a[i].z : a[i].w;
                acc[i][0] = fmaf(aj, b.x, acc[i][0]);
                acc[i][1] = fmaf(aj, b.y, acc[i][1]);
            }
        }
    }
    // per-row stats + exp
    int sb = (bh * NS + ks) * NT + w * 5;
    #pragma unroll
    for (int i = 0; i < 5; i++) {
        acc[i][0] *= SCALE; acc[i][1] *= SCALE;
        float mi = fmaxf(acc[i][0], acc[i][1]);
        #pragma unroll
        for (int o = 16; o; o >>= 1) mi = fmaxf(mi, __shfl_xor_sync(0xffffffffu, mi, o));
        float e0 = fexpf(acc[i][0] - mi);
        float e1 = fexpf(acc[i][1] - mi);
        acc[i][0] = e0; acc[i][1] = e1;
        float s = e0 + e1;
        #pragma unroll
        for (int o = 16; o; o >>= 1) s += __shfl_xor_sync(0xffffffffu, s, o);
        if (lane == 0) { g_pm[sb + i] = mi; g_psum[sb + i] = s; }
    }
    __syncthreads();                    // all warps done reading Kt
    float* P = Kt;                      // reuse
    #pragma unroll
    for (int i = 0; i < 5; i++)
        *(float2*)&P[(w * 5 + i) * 64 + lane * 2] = make_float2(acc[i][0], acc[i][1]);
    __syncthreads();

    // GEMM2: ctx_part[u][d] = sum_k P[u][k] * Vs[k][d]; lane owns 2 d's
    float acc2[5][2] = {};
    #pragma unroll 4
    for (int kk = 0; kk < 64; kk += 4) {
        float4 a[5];
        #pragma unroll
        for (int i = 0; i < 5; i++)
            a[i] = *(const float4*)&P[(w * 5 + i) * 64 + kk];
        #pragma unroll
        for (int j = 0; j < 4; j++) {
            float2 v = *(const float2*)&Vs[(kk + j) * Dq + lane * 2];
            #pragma unroll
            for (int i = 0; i < 5; i++) {
                float aj = (j == 0) ? a[i].x : (j == 1) ? a[i].y : (j == 2) ? a[i].z : a[i].w;
                acc2[i][0] = fmaf(aj, v.x, acc2[i][0]);
                acc2[i][1] = fmaf(aj, v.y, acc2[i][1]);
            }
        }
    }
    #pragma unroll
    for (int i = 0; i < 5; i++)
        *(float2*)&g_part[((size_t)(ks * BH + bh) * NT + w * 5 + i) * Dq + lane * 2]
            = make_float2(acc2[i][0], acc2[i][1]);
}

// ---------------- kernel 6: combine splits + scatter ---------------------
__global__ void k_comb(float* __restrict__ out) {
    int i = blockIdx.x * 256 + threadIdx.x;   // BH*NT*Dq = 81920
    if (i >= BH * NT * Dq) return;
    int d = i & 63;
    int r = i >> 6;
    int u = r % NT;
    int bh = r / NT;
    float M = -CUDART_INF_F;
    #pragma unroll 8
    for (int s = 0; s < NS; s++)
        M = fmaxf(M, g_pm[(bh * NS + s) * NT + u]);
    float sum = 0.f, ctx = 0.f;
    #pragma unroll 4
    for (int s = 0; s < NS; s++) {
        float wgt = fexpf(g_pm[(bh * NS + s) * NT + u] - M);
        sum = fmaf(g_psum[(bh * NS + s) * NT + u], wgt, sum);
        ctx = fmaf(g_part[((size_t)(s * BH + bh) * NT + u) * Dq + d], wgt, ctx);
    }
    int qi = g_top[bh * NT + u];
    out[((size_t)bh * Lq + qi) * Dq + d] = ctx / sum;
}

// ---------------- launch ---------------------------------------------------
extern "C" void kernel_launch(void* const* d_in, const int* in_sizes, int n_in,
                              void* d_out, int out_size) {
    const float* Q = (const float*)d_in[0];
    const float* K = (const float*)d_in[1];
    const float* V = (const float*)d_in[2];
    const int* idxs = (const int*)d_in[3];
    float* out = (float*)d_out;

    // order: NEW k_M is user launch #4 (profiled).
    const int NF4 = BH * Lq * Dq / 4;
    k_vmean<<<BH, 256>>>(V);                                  // 1
    k_fill<<<NF4 / 2 / 256, 256>>>((float4*)out, 0);          // 2
    k_fill<<<NF4 / 2 / 256, 256>>>((float4*)out, NF4 / 2);    // 3
    k_M<<<(BH * Lq) / 8, 256>>>(Q, K, idxs);                  // 4  <-- profiled
    k_topk<<<BH, 256>>>();                                    // 5
    k_flash<<<BH * NS, 256>>>(Q, K, V);                       // 6
    k_comb<<<(BH * NT * Dq + 255) / 256, 256>>>(out);         // 7
}

// round 17
// speedup vs baseline: 1.4046x; 1.4046x over previous
#include <cuda_runtime.h>
#include <cuda_bf16.h>
#include <math_constants.h>

// Problem constants (fixed by setup_inputs)
#define Bq 4
#define Hq 8
#define BH 32          // B*H
#define Lq 2048
#define Dq 64
#define SK 40          // sample_k
#define NT 40          // n_top
#define NS 32          // key splits in flash kernel (64 keys each)
#define SCALE 0.125f   // 1/sqrt(64)

// ---------------- scratch (device globals; no allocation) ----------------
__device__ float g_M[BH * Lq];                 // 256 KB
__device__ int   g_top[BH * NT];               // 5 KB
__device__ float g_vmean[BH * Dq];             // 8 KB
__device__ float g_pm[NS * BH * NT];           // per-split row max
__device__ float g_psum[NS * BH * NT];         // per-split exp-sum
__device__ float g_part[(size_t)NS * BH * NT * Dq];  // 10.5 MB partial ctx

// Fast exp on the FMA pipe: exp(x) = 2^(x*log2e), deg-6 poly + exponent bits.
__device__ __forceinline__ float fexpf(float x) {
    float y = x * 1.4426950408889634f;
    y = fmaxf(y, -125.0f);
    float r = rintf(y);
    float f = y - r;
    float p = 1.5403530e-4f;
    p = fmaf(p, f, 1.3333558e-3f);
    p = fmaf(p, f, 9.6181291e-3f);
    p = fmaf(p, f, 5.5504109e-2f);
    p = fmaf(p, f, 2.4022651e-1f);
    p = fmaf(p, f, 6.9314718e-1f);
    p = fmaf(p, f, 1.0f);
    return p * __int_as_float(((int)r + 127) << 23);
}

// ---------------- fold: transpose-reduce (V arrays, V/2 shuffles) --------
template<int O, int V>
__device__ __forceinline__ void fold(float* p, int lane) {
    bool hi = (lane & O) != 0;
    #pragma unroll
    for (int j = 0; j < V / 2; j++) {
        float send = hi ? p[j] : p[j + V / 2];
        float keep = hi ? p[j + V / 2] : p[j];
        p[j] = keep + __shfl_xor_sync(0xffffffffu, send, O);
    }
}

__device__ __forceinline__ float dot16(const float* __restrict__ Kb, float2 q,
                                       int e, int base, int lane) {
    float p[16];
    #pragma unroll
    for (int j = 0; j < 16; j++) {
        int idx = __shfl_sync(0xffffffffu, e, base + j);
        float2 k = ((const float2*)(Kb + (size_t)idx * Dq))[lane];
        p[j] = q.x * k.x + q.y * k.y;
    }
    fold<16, 16>(p, lane);
    fold<8, 8>(p, lane);
    fold<4, 4>(p, lane);
    fold<2, 2>(p, lane);
    p[0] += __shfl_xor_sync(0xffffffffu, p[0], 1);
    return p[0];
}

__device__ __forceinline__ float dot8(const float* __restrict__ Kb, float2 q,
                                      int e, int lane) {
    float p[8];
    #pragma unroll
    for (int j = 0; j < 8; j++) {
        int idx = __shfl_sync(0xffffffffu, e, j);
        float2 k = ((const float2*)(Kb + (size_t)idx * Dq))[lane];
        p[j] = q.x * k.x + q.y * k.y;
    }
    fold<16, 8>(p, lane);
    fold<8, 4>(p, lane);
    fold<4, 2>(p, lane);
    p[0] += __shfl_xor_sync(0xffffffffu, p[0], 2);
    p[0] += __shfl_xor_sync(0xffffffffu, p[0], 1);
    return p[0];
}

// ---------------- kernel 1: M[bh,l] = max_s q.k - sum_s/L ----------------
// (round-10 measured-best version: LDG.64 gathers, transpose-fold reduce)
__global__ void k_M(const float* __restrict__ Q, const float* __restrict__ K,
                    const int* __restrict__ idxs) {
    int w = blockIdx.x * 8 + (threadIdx.x >> 5);   // query id (bh*2048 + l)
    int lane = threadIdx.x & 31;
    int bh = w >> 11;
    int l  = w & (Lq - 1);
    float2 q = ((const float2*)(Q + (size_t)w * Dq))[lane];
    const float* Kb = K + (size_t)bh * Lq * Dq;
    int e0 = idxs[l * SK + lane];
    int e1 = (lane < 8) ? idxs[l * SK + 32 + lane] : 0;

    float a = dot16(Kb, q, e0, 0, lane);
    float b = dot16(Kb, q, e0, 16, lane);
    float c = dot8(Kb, q, e1, lane);

    float mx = fmaxf(fmaxf(a, b), c);
    float sm = 0.5f * (a + b) + 0.25f * c;
    #pragma unroll
    for (int o = 16; o; o >>= 1) {
        mx = fmaxf(mx, __shfl_xor_sync(0xffffffffu, mx, o));
        sm += __shfl_xor_sync(0xffffffffu, sm, o);
    }
    if (lane == 0) g_M[w] = mx - sm * (1.0f / (float)Lq);
}

// ---------------- kernel 2: top-40 per (b,h), 4-level radix select -------
__global__ void k_topk() {
    __shared__ int hist[8][256];
    __shared__ int suf[257];
    __shared__ int wred[8];
    __shared__ int s_T, s_cnt, s_min;
    int bh = blockIdx.x;
    int t = threadIdx.x, lane = t & 31, w = t >> 5;

    unsigned key[8];
    #pragma unroll
    for (int j = 0; j < 8; j++) {
        unsigned u = __float_as_uint(g_M[bh * Lq + t * 8 + j]);
        key[j] = (u & 0x80000000u) ? ~u : (u | 0x80000000u);
    }
    unsigned prefix = 0;
    int need = NT;
    if (t == 0) s_cnt = 0;

    #pragma unroll
    for (int level = 0; level < 4; level++) {
        int shift = 24 - 8 * level;
        for (int b = t; b < 8 * 256; b += 256) (&hist[0][0])[b] = 0;
        __syncthreads();
        #pragma unroll
        for (int j = 0; j < 8; j++) {
            bool match = (level == 0) || ((key[j] >> (shift + 8)) == prefix);
            if (match) atomicAdd(&hist[w][(key[j] >> shift) & 255u], 1);
        }
        __syncthreads();
        int h = 0;
        #pragma unroll
        for (int ww = 0; ww < 8; ww++) h += hist[ww][t];
        int sv = h;
        #pragma unroll
        for (int off = 1; off < 32; off <<= 1) {
            int v = __shfl_down_sync(0xffffffffu, sv, off);
            if (lane + off < 32) sv += v;
        }
        int wtot = __shfl_sync(0xffffffffu, sv, 0);
        if (lane == 0) wred[w] = wtot;
        __syncthreads();
        int higher = 0;
        #pragma unroll
        for (int ww = 0; ww < 8; ww++) if (ww > w) higher += wred[ww];
        suf[t] = sv + higher;
        if (t == 0) suf[256] = 0;
        __syncthreads();
        if (suf[t] >= need && suf[t + 1] < need) s_T = t;
        __syncthreads();
        int T = s_T;
        #pragma unroll
        for (int j = 0; j < 8; j++) {
            bool match = (level == 0) || ((key[j] >> (shift + 8)) == prefix);
            if (match && (int)((key[j] >> shift) & 255u) > T) {
                int p = atomicAdd(&s_cnt, 1);
                g_top[bh * NT + p] = t * 8 + j;
            }
        }
        need -= suf[T + 1];
        prefix = (prefix << 8) | (unsigned)T;
        __syncthreads();
    }

    for (int it = 0; it < need; it++) {
        int mi = Lq;
        #pragma unroll
        for (int j = 0; j < 8; j++)
            if (key[j] == prefix) mi = min(mi, t * 8 + j);
        #pragma unroll
        for (int off = 16; off; off >>= 1)
            mi = min(mi, __shfl_xor_sync(0xffffffffu, mi, off));
        if (lane == 0) wred[w] = mi;
        __syncthreads();
        if (t == 0) {
            int m = wred[0];
            #pragma unroll
            for (int ww = 1; ww < 8; ww++) m = min(m, wred[ww]);
            s_min = m;
            g_top[bh * NT + (NT - need) + it] = m;
        }
        __syncthreads();
        int m = s_min;
        if (m >= t * 8 && m < t * 8 + 8) key[m - t * 8] = 0u;
        __syncthreads();
    }
}

// ---------------- kernel 3: V mean over L per (b,h), float4 --------------
__global__ void k_vmean(const float* __restrict__ V) {
    __shared__ float4 ps[256];
    int bh = blockIdx.x;
    int t = threadIdx.x;
    int d4 = t & 15, part = t >> 4;
    const float4* Vb = (const float4*)(V + (size_t)bh * Lq * Dq);
    float4 s = make_float4(0.f, 0.f, 0.f, 0.f);
    int k0 = part * 128;
    for (int k = k0; k < k0 + 128; k++) {
        float4 v = Vb[(size_t)k * 16 + d4];
        s.x += v.x; s.y += v.y; s.z += v.z; s.w += v.w;
    }
    ps[t] = s;
    __syncthreads();
    if (t < 16) {
        float4 a = ps[t];
        #pragma unroll
        for (int pI = 1; pI < 16; pI++) {
            float4 v = ps[pI * 16 + t];
            a.x += v.x; a.y += v.y; a.z += v.z; a.w += v.w;
        }
        const float inv = 1.0f / (float)Lq;
        a.x *= inv; a.y *= inv; a.z *= inv; a.w *= inv;
        ((float4*)g_vmean)[bh * 16 + t] = a;
    }
}

// ---------------- kernel 4: broadcast V_mean (4 stores/thread) -----------
__global__ void k_fill(float4* __restrict__ out4) {
    int base = blockIdx.x * 1024 + threadIdx.x;   // 1024 blocks x 256 thr x 4
    #pragma unroll
    for (int r = 0; r < 4; r++) {
        int i = base + r * 256;
        out4[i] = ((const float4*)g_vmean)[(((i >> 15)) << 4) | (i & 15)];
    }
}

// ---------------- kernel 5: fused flash attention over 64-key split ------
// grid = BH*NS = 1024 blocks, 256 threads. Smem ALIASED by phase:
//   phase1: qs [0,2560) + Kt [2560,6784)     (GEMM1)
//   phase2: P  [0,2560) + Vs [2560,6656)     (GEMM2; overwrites dead qs/Kt)
// 27 KB static smem -> 6 blocks/SM (48 resident warps vs 29 before).
__global__ void k_flash(const float* __restrict__ Q,
                        const float* __restrict__ K,
                        const float* __restrict__ V) {
    __shared__ float sm[6784];         // 26.5 KB
    __shared__ int stop[NT];
    float* qs = sm;                    // phase1
    float* Kt = sm + 2560;             // phase1, pad-66 rows
    float* P  = sm;                    // phase2
    float* Vs = sm + 2560;             // phase2
    int bh = blockIdx.x >> 5;
    int ks = blockIdx.x & 31;
    int t = threadIdx.x;               // 256
    const float* Qb = Q + (size_t)bh * Lq * Dq;
    const float* Kb = K + (size_t)bh * Lq * Dq;
    const float* Vb = V + (size_t)bh * Lq * Dq;
    if (t < NT) stop[t] = g_top[bh * NT + t];
    __syncthreads();
    for (int j = t; j < NT * Dq; j += 256) {
        int u = j >> 6, d = j & 63;
        qs[j] = Qb[(size_t)stop[u] * Dq + d];
    }
    for (int j = t; j < 64 * Dq; j += 256) {
        int r = j >> 6, d = j & 63;
        Kt[d * 66 + r] = Kb[(size_t)(ks * 64 + r) * Dq + d];
    }
    __syncthreads();

    int w = t >> 5, lane = t & 31;     // warp w: queries w*5..w*5+4; lane: 2 keys
    float acc[5][2] = {};
    #pragma unroll
    for (int dc = 0; dc < Dq; dc += 4) {
        float4 a[5];
        #pragma unroll
        for (int i = 0; i < 5; i++)
            a[i] = *(const float4*)&qs[(w * 5 + i) * Dq + dc];
        #pragma unroll
        for (int j = 0; j < 4; j++) {
            float2 b = *(const float2*)&Kt[(dc + j) * 66 + lane * 2];
            #pragma unroll
            for (int i = 0; i < 5; i++) {
                float aj = (j == 0) ? a[i].x : (j == 1) ? a[i].y : (j == 2) ? a[i].z : a[i].w;
                acc[i][0] = fmaf(aj, b.x, acc[i][0]);
                acc[i][1] = fmaf(aj, b.y, acc[i][1]);
            }
        }
    }
    // per-row stats + exp (batched butterflies)
    float m[5], s[5];
    #pragma unroll
    for (int i = 0; i < 5; i++) {
        acc[i][0] *= SCALE; acc[i][1] *= SCALE;
        m[i] = fmaxf(acc[i][0], acc[i][1]);
    }
    #pragma unroll
    for (int o = 16; o; o >>= 1) {
        #pragma unroll
        for (int i = 0; i < 5; i++)
            m[i] = fmaxf(m[i], __shfl_xor_sync(0xffffffffu, m[i], o));
    }
    #pragma unroll
    for (int i = 0; i < 5; i++) {
        acc[i][0] = fexpf(acc[i][0] - m[i]);
        acc[i][1] = fexpf(acc[i][1] - m[i]);
        s[i] = acc[i][0] + acc[i][1];
    }
    #pragma unroll
    for (int o = 16; o; o >>= 1) {
        #pragma unroll
        for (int i = 0; i < 5; i++)
            s[i] += __shfl_xor_sync(0xffffffffu, s[i], o);
    }
    if (lane == 0) {
        int sb = (bh * NS + ks) * NT + w * 5;
        #pragma unroll
        for (int i = 0; i < 5; i++) { g_pm[sb + i] = m[i]; g_psum[sb + i] = s[i]; }
    }
    __syncthreads();                    // qs + Kt reads complete -> dead

    // phase2 staging: P into [0,2560), Vs into [2560,6656)
    #pragma unroll
    for (int i = 0; i < 5; i++)
        *(float2*)&P[(w * 5 + i) * 64 + lane * 2] = make_float2(acc[i][0], acc[i][1]);
    for (int j = t; j < 64 * Dq; j += 256) Vs[j] = Vb[(size_t)ks * 64 * Dq + j];
    __syncthreads();

    // GEMM2: ctx_part[u][d] = sum_k P[u][k] * Vs[k][d]; lane owns 2 d's
    float acc2[5][2] = {};
    #pragma unroll 4
    for (int kk = 0; kk < 64; kk += 4) {
        float4 a[5];
        #pragma unroll
        for (int i = 0; i < 5; i++)
            a[i] = *(const float4*)&P[(w * 5 + i) * 64 + kk];
        #pragma unroll
        for (int j = 0; j < 4; j++) {
            float2 v = *(const float2*)&Vs[(kk + j) * Dq + lane * 2];
            #pragma unroll
            for (int i = 0; i < 5; i++) {
                float aj = (j == 0) ? a[i].x : (j == 1) ? a[i].y : (j == 2) ? a[i].z : a[i].w;
                acc2[i][0] = fmaf(aj, v.x, acc2[i][0]);
                acc2[i][1] = fmaf(aj, v.y, acc2[i][1]);
            }
        }
    }
    #pragma unroll
    for (int i = 0; i < 5; i++)
        *(float2*)&g_part[((size_t)(ks * BH + bh) * NT + w * 5 + i) * Dq + lane * 2]
            = make_float2(acc2[i][0], acc2[i][1]);
}

// ---------------- kernel 6: combine splits + scatter ---------------------
__global__ void k_comb(float* __restrict__ out) {
    int i = blockIdx.x * 256 + threadIdx.x;   // BH*NT*Dq = 81920
    if (i >= BH * NT * Dq) return;
    int d = i & 63;
    int r = i >> 6;
    int u = r % NT;
    int bh = r / NT;
    float M = -CUDART_INF_F;
    #pragma unroll 8
    for (int s = 0; s < NS; s++)
        M = fmaxf(M, g_pm[(bh * NS + s) * NT + u]);
    float sum = 0.f, ctx = 0.f;
    #pragma unroll 4
    for (int s = 0; s < NS; s++) {
        float wgt = fexpf(g_pm[(bh * NS + s) * NT + u] - M);
        sum = fmaf(g_psum[(bh * NS + s) * NT + u], wgt, sum);
        ctx = fmaf(g_part[((size_t)(s * BH + bh) * NT + u) * Dq + d], wgt, ctx);
    }
    int qi = g_top[bh * NT + u];
    out[((size_t)bh * Lq + qi) * Dq + d] = ctx / sum;
}

// ---------------- launch ---------------------------------------------------
extern "C" void kernel_launch(void* const* d_in, const int* in_sizes, int n_in,
                              void* d_out, int out_size) {
    const float* Q = (const float*)d_in[0];
    const float* K = (const float*)d_in[1];
    const float* V = (const float*)d_in[2];
    const int* idxs = (const int*)d_in[3];
    float* out = (float*)d_out;

    // order: k_flash (27 KB smem-aliased version) is user launch #4.
    k_M<<<(BH * Lq) / 8, 256>>>(Q, K, idxs);                  // 1
    k_topk<<<BH, 256>>>();                                    // 2
    k_vmean<<<BH, 256>>>(V);                                  // 3
    k_flash<<<BH * NS, 256>>>(Q, K, V);                       // 4  <-- profiled
    k_fill<<<(BH * Lq * Dq / 4) / 1024, 256>>>((float4*)out); // 5
    k_comb<<<(BH * NT * Dq + 255) / 256, 256>>>(out);         // 6
}